// round 16
// baseline (speedup 1.0000x reference)
#include <cuda_runtime.h>
#include <math.h>

#define BATCH 32
#define HH 76
#define WW 76
#define AA 3
#define NCLS 80
#define SPAT (HH*WW)          /* 5776 */
#define NQ   (SPAT/4)         /* 1444 */
#define NCAND (SPAT*AA)       /* 17328 */
#define MAXDET 300
#define NWORDS 10             /* ceil(300/32) */
#define X_ELEMS (BATCH * (AA*(5+NCLS)) * SPAT)   /* 47,174,400 */

// ---------------- scratch (device-code-only references) ----------------
__device__ float              g_masked[BATCH*NCAND];
__device__ unsigned char      g_label [BATCH*NCAND];
__device__ int                g_selidx[BATCH*MAXDET];
__device__ float              g_selmask[BATCH*MAXDET];
__device__ unsigned long long g_keys[(size_t)BATCH*NCAND];
__device__ int                g_cnt[BATCH];

// ---------- XLA LogisticExpander: logistic(x) = 1/(1+exp(-x)) ----------
__device__ __forceinline__ float xla_sigmoid(float x) {
    return __fdiv_rn(1.0f, __fadd_rn(1.0f, expf(-x)));
}

__global__ void k_zero() { if (threadIdx.x < BATCH) g_cnt[threadIdx.x] = 0; }

// ================= K1: streaming decode + valid-candidate compaction ======
// thread = 4 consecutive spatial positions for one (anchor, batch).
__global__ __launch_bounds__(128) void k_decode(const float* __restrict__ x) {
    int q = blockIdx.x * blockDim.x + threadIdx.x;
    bool live = (q < NQ);
    int qc = live ? q : (NQ - 1);
    int a = blockIdx.y, b = blockIdx.z;
    int s0 = qc * 4;
    const float4* p4 = (const float4*)(x + ((size_t)b * (AA*85) + (size_t)a * 85) * SPAT);

    // pass 1: running max over 80 class logits (vectorized)
    float4 mv = __ldg(p4 + 5 * NQ + qc);
    #pragma unroll 16
    for (int f = 1; f < NCLS; ++f) {
        float4 v = __ldg(p4 + (5 + f) * NQ + qc);
        mv.x = fmaxf(mv.x, v.x); mv.y = fmaxf(mv.y, v.y);
        mv.z = fmaxf(mv.z, v.z); mv.w = fmaxf(mv.w, v.w);
    }
    float win[4] = { __fadd_rn(mv.x, -0.004f), __fadd_rn(mv.y, -0.004f),
                     __fadd_rn(mv.z, -0.004f), __fadd_rn(mv.w, -0.004f) };
    float smax[4] = {-1.f, -1.f, -1.f, -1.f};
    int   lab [4] = {0, 0, 0, 0};

    // pass 2 (L1/L2 re-read): exact max(sigmoid) + first-index argmax.
    // rounded exp-form sigmoid is monotone except within ~1ulp windows
    // (< 0.004 in logit space) and saturation-to-1 (logit >= ~17.3).
    #pragma unroll 8
    for (int f = 0; f < NCLS; ++f) {
        float4 v = __ldg(p4 + (5 + f) * NQ + qc);
        float vv[4] = {v.x, v.y, v.z, v.w};
        #pragma unroll
        for (int c = 0; c < 4; ++c) {
            if (vv[c] >= win[c] || vv[c] >= 17.0f) {
                float sv = xla_sigmoid(vv[c]);
                if (sv > smax[c]) { smax[c] = sv; lab[c] = f; }  // strict >: first idx
            }
        }
    }

    float4 to = __ldg(p4 + 4 * NQ + qc);
    float tv[4] = {to.x, to.y, to.z, to.w};
    int lane = threadIdx.x & 31;
    #pragma unroll
    for (int c = 0; c < 4; ++c) {
        float obj_s = xla_sigmoid(tv[c]);
        float score = __fmul_rn(smax[c], obj_s);
        bool valid = live && (obj_s >= 0.5f) && (score >= 0.05f);
        int idx = (s0 + c) * AA + a;          // reference flatten order [H,W,A]
        if (live) {
            g_masked[(size_t)b * NCAND + idx] = valid ? score : -1.0f;
            g_label [(size_t)b * NCAND + idx] = (unsigned char)lab[c];
        }
        // warp-aggregated append of (ord<<32 | ~idx) keys
        unsigned bal = __ballot_sync(0xFFFFFFFFu, valid);
        if (bal) {
            int leader = __ffs((int)bal) - 1;
            int base_i = 0;
            if (lane == leader) base_i = atomicAdd(&g_cnt[b], __popc(bal));
            base_i = __shfl_sync(0xFFFFFFFFu, base_i, leader);
            if (valid) {
                unsigned ordv = __float_as_uint(score) | 0x80000000u; // score > 0
                unsigned long long key = ((unsigned long long)ordv << 32) |
                                         (unsigned long long)(0xFFFFFFFFu - (unsigned)idx);
                g_keys[(size_t)b * NCAND + base_i +
                       __popc(bal & ((1u << lane) - 1u))] = key;
            }
        }
    }
}

// ================= K2: exact top-300 per batch (64-bit radix select) ======
__global__ __launch_bounds__(1024) void k_select() {
    const int bdim = 1024;
    int b = blockIdx.x, tid = threadIdx.x, lane = tid & 31;
    const unsigned long long* ks = g_keys + (size_t)b * NCAND;
    int cnt = g_cnt[b];

    __shared__ unsigned hist[256];
    __shared__ int S[256];
    __shared__ unsigned long long keys[512];
    __shared__ int sh_bin, sh_next, sh_cnt;

    for (int i = tid; i < 512; i += bdim) keys[i] = 0ull;
    if (tid == 0) sh_cnt = 0;
    __syncthreads();

    if (cnt >= MAXDET) {
        unsigned long long prefix = 0, pmask = 0;
        int k = MAXDET;
        for (int pass = 0; pass < 8; ++pass) {
            int shift = 56 - 8 * pass;
            if (tid < 256) hist[tid] = 0;
            __syncthreads();
            for (int base_i = 0; base_i < cnt; base_i += bdim) {
                int i = base_i + tid;
                unsigned key = 0x100u;
                if (i < cnt) {
                    unsigned long long u = ks[i];
                    if ((u & pmask) == prefix) key = (unsigned)((u >> shift) & 255);
                }
                unsigned grp = __match_any_sync(0xFFFFFFFFu, key);
                if (key != 0x100u && lane == (__ffs((int)grp) - 1))
                    atomicAdd(&hist[key], (unsigned)__popc(grp));
            }
            __syncthreads();
            // parallel suffix sum: S[i] = sum_{j>=i} hist[j]
            if (tid < 256) S[tid] = (int)hist[tid];
            __syncthreads();
            for (int off = 1; off < 256; off <<= 1) {
                int add = 0;
                if (tid < 256 && tid + off < 256) add = S[tid + off];
                __syncthreads();
                if (tid < 256) S[tid] += add;
                __syncthreads();
            }
            if (tid < 256) {
                int snext = (tid == 255) ? 0 : S[tid + 1];
                if (S[tid] >= k && snext < k) { sh_bin = tid; sh_next = snext; }
            }
            __syncthreads();
            prefix |= ((unsigned long long)sh_bin << shift);
            pmask  |= (0xFFull << shift);
            k -= sh_next;
            __syncthreads();
        }
        unsigned long long T = prefix;   // exact 300th-largest key (keys distinct)
        for (int base_i = 0; base_i < cnt; base_i += bdim) {
            int i = base_i + tid;
            if (i < cnt) {
                unsigned long long u = ks[i];
                if (u >= T) {
                    int p = atomicAdd(&sh_cnt, 1);
                    if (p < 512) keys[p] = u;     // exactly 300 in exact path
                }
            }
        }
        __syncthreads();
    } else {
        // ---- fallback (cnt < 300): valid keys + lowest-index invalids ----
        __shared__ int wsum[32], woff[33]; __shared__ int sh_run;
        for (int i = tid; i < cnt; i += bdim) keys[i] = ks[i];
        if (tid == 0) sh_run = 0;
        __syncthreads();
        const float* ms = g_masked + (size_t)b * NCAND;
        int wrp = tid >> 5;
        for (int base_i = 0; base_i < NCAND; base_i += bdim) {
            int i = base_i + tid;
            int flag = (i < NCAND) && (ms[i] < 0.0f);
            unsigned bal = __ballot_sync(0xFFFFFFFFu, flag);
            if (lane == 0) wsum[wrp] = __popc(bal);
            __syncthreads();
            if (tid == 0) {
                int acc = 0;
                for (int w = 0; w < 32; ++w) { woff[w] = acc; acc += wsum[w]; }
                woff[32] = acc;
            }
            __syncthreads();
            if (flag) {
                int pos = sh_run + woff[wrp] + __popc(bal & ((1u << lane) - 1u));
                int dst = cnt + pos;
                if (pos < MAXDET - cnt && dst < 512) {
                    unsigned ordv = ~__float_as_uint(-1.0f);   // ord(-1.0) = 0x407FFFFF
                    keys[dst] = ((unsigned long long)ordv << 32) |
                                (unsigned long long)(0xFFFFFFFFu - (unsigned)i);
                }
            }
            __syncthreads();
            if (tid == 0) sh_run += woff[32];
            __syncthreads();
        }
    }

    // bitonic sort 512 keys, descending (zero pad sorts last)
    for (int kk = 2; kk <= 512; kk <<= 1) {
        for (int j = kk >> 1; j > 0; j >>= 1) {
            if (tid < 512) {
                int ixj = tid ^ j;
                if (ixj > tid) {
                    unsigned long long va = keys[tid], vc = keys[ixj];
                    bool desc = ((tid & kk) == 0);
                    if (desc ? (va < vc) : (va > vc)) { keys[tid] = vc; keys[ixj] = va; }
                }
            }
            __syncthreads();
        }
    }

    for (int j = tid; j < MAXDET; j += bdim) {
        unsigned long long key = keys[j];
        unsigned uo = (unsigned)(key >> 32);
        int idx = (int)(0xFFFFFFFFu - (unsigned)(key & 0xFFFFFFFFull));
        if (idx < 0 || idx >= NCAND) idx = 0;
        float score = (uo & 0x80000000u) ? __uint_as_float(uo & 0x7FFFFFFFu)
                                         : __uint_as_float(~uo);
        g_selidx [b * MAXDET + j] = idx;
        g_selmask[b * MAXDET + j] = score;
    }
}

// ======== K3: fused box decode + parallel-bitmask NMS (block per batch) ====
__global__ __launch_bounds__(1024) void k_boxnms(const float* __restrict__ x,
                                                 const float* __restrict__ anchors,
                                                 float* __restrict__ out) {
    __shared__ float4   bx[MAXDET];
    __shared__ unsigned sup[MAXDET * NWORDS];
    __shared__ unsigned keepw_s[NWORDS];
    int b = blockIdx.x, tid = threadIdx.x;

    // ---- Phase A: decode selected boxes; write boxes/scores/labels ----
    if (tid < MAXDET) {
        int t = b * MAXDET + tid;
        int idx = g_selidx[t];
        float m = g_selmask[t];
        int a = idx % AA;
        int s = idx / AA;
        int hh = s / WW, ww = s % WW;

        const float* p = x + ((size_t)b * (AA * 85) + (size_t)a * 85) * SPAT + s;
        float t0 = __ldg(p), t1 = __ldg(p + SPAT);
        float t2 = __ldg(p + 2 * SPAT), t3 = __ldg(p + 3 * SPAT);

        float sx = __fsub_rn(__fmul_rn(1.2f, xla_sigmoid(t0)), 0.1f);
        float sy = __fsub_rn(__fmul_rn(1.2f, xla_sigmoid(t1)), 0.1f);
        float bxc = __fdiv_rn(__fadd_rn(sx, (float)ww), (float)WW);
        float byc = __fdiv_rn(__fadd_rn(sy, (float)hh), (float)HH);
        float bw = fminf(fmaxf(__fmul_rn(expf(t2), __ldg(anchors + a * 2 + 0)), 0.0f), 2.0f);
        float bh = fminf(fmaxf(__fmul_rn(expf(t3), __ldg(anchors + a * 2 + 1)), 0.0f), 2.0f);
        float x1 = __fsub_rn(bxc, __fmul_rn(0.5f, bw));
        float y1 = __fsub_rn(byc, __fmul_rn(0.5f, bh));
        float x2 = __fadd_rn(x1, bw);
        float y2 = __fadd_rn(y1, bh);
        x1 = fminf(fmaxf(x1, 0.0f), 1.0f);
        y1 = fminf(fmaxf(y1, 0.0f), 1.0f);
        x2 = fminf(fmaxf(x2, 0.0f), 1.0f);
        y2 = fminf(fmaxf(y2, 0.0f), 1.0f);

        bx[tid] = make_float4(x1, y1, x2, y2);
        float* ob = out + (size_t)t * 4;
        ob[0] = x1; ob[1] = y1; ob[2] = x2; ob[3] = y2;
        out[(size_t)BATCH * MAXDET * 4 + t] = (m >= 0.0f) ? m : 0.0f;
        out[(size_t)BATCH * MAXDET * 5 + t] = (float)g_label[(size_t)b * NCAND + idx];
    }
    __syncthreads();

    // ---- Phase B: suppression bit matrix (iou > 0.7, j > i) in parallel ----
    for (int task = tid; task < MAXDET * NWORDS; task += blockDim.x) {
        int i = task / NWORDS, w = task % NWORDS;
        float4 bi = bx[i];
        float ai = __fmul_rn(__fsub_rn(bi.z, bi.x), __fsub_rn(bi.w, bi.y));
        unsigned bits = 0;
        int j0 = w * 32;
        #pragma unroll 8
        for (int jj = 0; jj < 32; ++jj) {
            int j = j0 + jj;
            if (j > i && j < MAXDET) {
                float4 bj = bx[j];
                float lx = fmaxf(bi.x, bj.x), ly = fmaxf(bi.y, bj.y);
                float rx = fminf(bi.z, bj.z), ry = fminf(bi.w, bj.w);
                float iw = fmaxf(__fsub_rn(rx, lx), 0.0f);
                float ih = fmaxf(__fsub_rn(ry, ly), 0.0f);
                float inter = __fmul_rn(iw, ih);
                float aj = __fmul_rn(__fsub_rn(bj.z, bj.x), __fsub_rn(bj.w, bj.y));
                float den = __fadd_rn(__fsub_rn(__fadd_rn(ai, aj), inter), 1e-9f);
                float iou = __fdiv_rn(inter, den);
                if (iou > 0.7f) bits |= (1u << jj);
            }
        }
        sup[task] = bits;
    }
    __syncthreads();

    // ---- Phase C: sequential greedy scan on one warp (bit ops only) ----
    if (tid < 32) {
        int l = tid;
        unsigned kw = 0;
        if (l < NWORDS) {
            for (int jj = 0; jj < 32; ++jj) {
                int j = l * 32 + jj;
                if (j < MAXDET && g_selmask[b * MAXDET + j] >= 0.0f) kw |= (1u << jj);
            }
        }
        for (int i = 0; i < MAXDET; ++i) {
            unsigned wrd = __shfl_sync(0xFFFFFFFFu, kw, i >> 5);
            if ((wrd >> (i & 31)) & 1u) {            // warp-uniform branch
                if (l < NWORDS) kw &= ~sup[i * NWORDS + l];
            }
        }
        if (l < NWORDS) keepw_s[l] = kw;
    }
    __syncthreads();
    for (int j = tid; j < MAXDET; j += blockDim.x)
        out[(size_t)BATCH * MAXDET * 6 + b * MAXDET + j] =
            ((keepw_s[j >> 5] >> (j & 31)) & 1u) ? 1.0f : 0.0f;
}

// ================= launch =================
extern "C" void kernel_launch(void* const* d_in, const int* in_sizes, int n_in,
                              void* d_out, int out_size) {
    (void)out_size;
    const float* x       = (const float*)d_in[0];
    const float* anchors = (const float*)d_in[1];
    if (n_in >= 2) {
        if (in_sizes[1] == X_ELEMS || in_sizes[0] < in_sizes[1]) {
            x = (const float*)d_in[1]; anchors = (const float*)d_in[0];
        }
    }
    float* out = (float*)d_out;

    k_zero<<<1, 32>>>();
    dim3 g1((NQ + 127) / 128, AA, BATCH);
    k_decode<<<g1, 128>>>(x);
    k_select<<<BATCH, 1024>>>();
    k_boxnms<<<BATCH, 1024>>>(x, anchors, out);
}

// round 17
// speedup vs baseline: 1.0009x; 1.0009x over previous
#include <cuda_runtime.h>
#include <math.h>

#define BATCH 32
#define HH 76
#define WW 76
#define AA 3
#define NCLS 80
#define SPAT (HH*WW)          /* 5776 */
#define NQ   (SPAT/4)         /* 1444 */
#define NCAND (SPAT*AA)       /* 17328 */
#define MAXDET 300
#define NWORDS 10             /* ceil(300/32) */
#define X_ELEMS (BATCH * (AA*(5+NCLS)) * SPAT)   /* 47,174,400 */

// ---------------- scratch (device-code-only references) ----------------
__device__ float              g_masked[BATCH*NCAND];
__device__ unsigned char      g_label [BATCH*NCAND];
__device__ int                g_selidx[BATCH*MAXDET];
__device__ float              g_selmask[BATCH*MAXDET];
__device__ unsigned long long g_keys[(size_t)BATCH*NCAND];
__device__ int                g_cnt[BATCH];

// ---------- XLA LogisticExpander: logistic(x) = 1/(1+exp(-x)) ----------
__device__ __forceinline__ float xla_sigmoid(float x) {
    return __fdiv_rn(1.0f, __fadd_rn(1.0f, expf(-x)));
}

__global__ void k_zero() { if (threadIdx.x < BATCH) g_cnt[threadIdx.x] = 0; }

// ================= K1: streaming decode + valid-candidate compaction ======
// thread = 4 consecutive spatial positions for one (anchor, batch).
__global__ __launch_bounds__(128) void k_decode(const float* __restrict__ x) {
    int q = blockIdx.x * blockDim.x + threadIdx.x;
    bool live = (q < NQ);
    int qc = live ? q : (NQ - 1);
    int a = blockIdx.y, b = blockIdx.z;
    int s0 = qc * 4;
    const float4* p4 = (const float4*)(x + ((size_t)b * (AA*85) + (size_t)a * 85) * SPAT);

    // pass 1: running max over 80 class logits (vectorized)
    float4 mv = __ldg(p4 + 5 * NQ + qc);
    #pragma unroll 16
    for (int f = 1; f < NCLS; ++f) {
        float4 v = __ldg(p4 + (5 + f) * NQ + qc);
        mv.x = fmaxf(mv.x, v.x); mv.y = fmaxf(mv.y, v.y);
        mv.z = fmaxf(mv.z, v.z); mv.w = fmaxf(mv.w, v.w);
    }
    float win[4] = { __fadd_rn(mv.x, -0.004f), __fadd_rn(mv.y, -0.004f),
                     __fadd_rn(mv.z, -0.004f), __fadd_rn(mv.w, -0.004f) };
    float smax[4] = {-1.f, -1.f, -1.f, -1.f};
    int   lab [4] = {0, 0, 0, 0};

    // pass 2 (L1/L2 re-read): exact max(sigmoid) + first-index argmax.
    // rounded exp-form sigmoid is monotone except within ~1ulp windows
    // (< 0.004 in logit space) and saturation-to-1 (logit >= ~17.3).
    #pragma unroll 8
    for (int f = 0; f < NCLS; ++f) {
        float4 v = __ldg(p4 + (5 + f) * NQ + qc);
        float vv[4] = {v.x, v.y, v.z, v.w};
        #pragma unroll
        for (int c = 0; c < 4; ++c) {
            if (vv[c] >= win[c] || vv[c] >= 17.0f) {
                float sv = xla_sigmoid(vv[c]);
                if (sv > smax[c]) { smax[c] = sv; lab[c] = f; }  // strict >: first idx
            }
        }
    }

    float4 to = __ldg(p4 + 4 * NQ + qc);
    float tv[4] = {to.x, to.y, to.z, to.w};
    int lane = threadIdx.x & 31;
    #pragma unroll
    for (int c = 0; c < 4; ++c) {
        float obj_s = xla_sigmoid(tv[c]);
        float score = __fmul_rn(smax[c], obj_s);
        bool valid = live && (obj_s >= 0.5f) && (score >= 0.05f);
        int idx = (s0 + c) * AA + a;          // reference flatten order [H,W,A]
        if (live) {
            g_masked[(size_t)b * NCAND + idx] = valid ? score : -1.0f;
            g_label [(size_t)b * NCAND + idx] = (unsigned char)lab[c];
        }
        // warp-aggregated append of (ord<<32 | ~idx) keys
        unsigned bal = __ballot_sync(0xFFFFFFFFu, valid);
        if (bal) {
            int leader = __ffs((int)bal) - 1;
            int base_i = 0;
            if (lane == leader) base_i = atomicAdd(&g_cnt[b], __popc(bal));
            base_i = __shfl_sync(0xFFFFFFFFu, base_i, leader);
            if (valid) {
                unsigned ordv = __float_as_uint(score) | 0x80000000u; // score > 0
                unsigned long long key = ((unsigned long long)ordv << 32) |
                                         (unsigned long long)(0xFFFFFFFFu - (unsigned)idx);
                g_keys[(size_t)b * NCAND + base_i +
                       __popc(bal & ((1u << lane) - 1u))] = key;
            }
        }
    }
}

// ================= K2: exact top-300 per batch (64-bit radix select) ======
__global__ __launch_bounds__(1024) void k_select() {
    const int bdim = 1024;
    int b = blockIdx.x, tid = threadIdx.x, lane = tid & 31;
    const unsigned long long* ks = g_keys + (size_t)b * NCAND;
    int cnt = g_cnt[b];

    __shared__ unsigned hist[256];
    __shared__ int S[256];
    __shared__ unsigned long long keys[512];
    __shared__ int sh_bin, sh_next, sh_cnt;

    for (int i = tid; i < 512; i += bdim) keys[i] = 0ull;
    if (tid == 0) sh_cnt = 0;
    __syncthreads();

    if (cnt >= MAXDET) {
        unsigned long long prefix = 0, pmask = 0;
        int k = MAXDET;
        for (int pass = 0; pass < 8; ++pass) {
            int shift = 56 - 8 * pass;
            if (tid < 256) hist[tid] = 0;
            __syncthreads();
            for (int base_i = 0; base_i < cnt; base_i += bdim) {
                int i = base_i + tid;
                unsigned key = 0x100u;
                if (i < cnt) {
                    unsigned long long u = ks[i];
                    if ((u & pmask) == prefix) key = (unsigned)((u >> shift) & 255);
                }
                unsigned grp = __match_any_sync(0xFFFFFFFFu, key);
                if (key != 0x100u && lane == (__ffs((int)grp) - 1))
                    atomicAdd(&hist[key], (unsigned)__popc(grp));
            }
            __syncthreads();
            // parallel suffix sum: S[i] = sum_{j>=i} hist[j]
            if (tid < 256) S[tid] = (int)hist[tid];
            __syncthreads();
            for (int off = 1; off < 256; off <<= 1) {
                int add = 0;
                if (tid < 256 && tid + off < 256) add = S[tid + off];
                __syncthreads();
                if (tid < 256) S[tid] += add;
                __syncthreads();
            }
            if (tid < 256) {
                int snext = (tid == 255) ? 0 : S[tid + 1];
                if (S[tid] >= k && snext < k) { sh_bin = tid; sh_next = snext; }
            }
            __syncthreads();
            prefix |= ((unsigned long long)sh_bin << shift);
            pmask  |= (0xFFull << shift);
            k -= sh_next;
            __syncthreads();
        }
        unsigned long long T = prefix;   // exact 300th-largest key (keys distinct)
        for (int base_i = 0; base_i < cnt; base_i += bdim) {
            int i = base_i + tid;
            if (i < cnt) {
                unsigned long long u = ks[i];
                if (u >= T) {
                    int p = atomicAdd(&sh_cnt, 1);
                    if (p < 512) keys[p] = u;     // exactly 300 in exact path
                }
            }
        }
        __syncthreads();
    } else {
        // ---- fallback (cnt < 300): valid keys + lowest-index invalids ----
        __shared__ int wsum[32], woff[33]; __shared__ int sh_run;
        for (int i = tid; i < cnt; i += bdim) keys[i] = ks[i];
        if (tid == 0) sh_run = 0;
        __syncthreads();
        const float* ms = g_masked + (size_t)b * NCAND;
        int wrp = tid >> 5;
        for (int base_i = 0; base_i < NCAND; base_i += bdim) {
            int i = base_i + tid;
            int flag = (i < NCAND) && (ms[i] < 0.0f);
            unsigned bal = __ballot_sync(0xFFFFFFFFu, flag);
            if (lane == 0) wsum[wrp] = __popc(bal);
            __syncthreads();
            if (tid == 0) {
                int acc = 0;
                for (int w = 0; w < 32; ++w) { woff[w] = acc; acc += wsum[w]; }
                woff[32] = acc;
            }
            __syncthreads();
            if (flag) {
                int pos = sh_run + woff[wrp] + __popc(bal & ((1u << lane) - 1u));
                int dst = cnt + pos;
                if (pos < MAXDET - cnt && dst < 512) {
                    unsigned ordv = ~__float_as_uint(-1.0f);   // ord(-1.0) = 0x407FFFFF
                    keys[dst] = ((unsigned long long)ordv << 32) |
                                (unsigned long long)(0xFFFFFFFFu - (unsigned)i);
                }
            }
            __syncthreads();
            if (tid == 0) sh_run += woff[32];
            __syncthreads();
        }
    }

    // bitonic sort 512 keys, descending (zero pad sorts last)
    for (int kk = 2; kk <= 512; kk <<= 1) {
        for (int j = kk >> 1; j > 0; j >>= 1) {
            if (tid < 512) {
                int ixj = tid ^ j;
                if (ixj > tid) {
                    unsigned long long va = keys[tid], vc = keys[ixj];
                    bool desc = ((tid & kk) == 0);
                    if (desc ? (va < vc) : (va > vc)) { keys[tid] = vc; keys[ixj] = va; }
                }
            }
            __syncthreads();
        }
    }

    for (int j = tid; j < MAXDET; j += bdim) {
        unsigned long long key = keys[j];
        unsigned uo = (unsigned)(key >> 32);
        int idx = (int)(0xFFFFFFFFu - (unsigned)(key & 0xFFFFFFFFull));
        if (idx < 0 || idx >= NCAND) idx = 0;
        float score = (uo & 0x80000000u) ? __uint_as_float(uo & 0x7FFFFFFFu)
                                         : __uint_as_float(~uo);
        g_selidx [b * MAXDET + j] = idx;
        g_selmask[b * MAXDET + j] = score;
    }
}

// ======== K3: fused box decode + parallel-bitmask NMS (block per batch) ====
__global__ __launch_bounds__(1024) void k_boxnms(const float* __restrict__ x,
                                                 const float* __restrict__ anchors,
                                                 float* __restrict__ out) {
    __shared__ float4   bx[MAXDET];
    __shared__ unsigned sup[MAXDET * NWORDS];
    __shared__ unsigned keepw_s[NWORDS];
    int b = blockIdx.x, tid = threadIdx.x;

    // ---- Phase A: decode selected boxes; write boxes/scores/labels ----
    if (tid < MAXDET) {
        int t = b * MAXDET + tid;
        int idx = g_selidx[t];
        float m = g_selmask[t];
        int a = idx % AA;
        int s = idx / AA;
        int hh = s / WW, ww = s % WW;

        const float* p = x + ((size_t)b * (AA * 85) + (size_t)a * 85) * SPAT + s;
        float t0 = __ldg(p), t1 = __ldg(p + SPAT);
        float t2 = __ldg(p + 2 * SPAT), t3 = __ldg(p + 3 * SPAT);

        float sx = __fsub_rn(__fmul_rn(1.2f, xla_sigmoid(t0)), 0.1f);
        float sy = __fsub_rn(__fmul_rn(1.2f, xla_sigmoid(t1)), 0.1f);
        float bxc = __fdiv_rn(__fadd_rn(sx, (float)ww), (float)WW);
        float byc = __fdiv_rn(__fadd_rn(sy, (float)hh), (float)HH);
        float bw = fminf(fmaxf(__fmul_rn(expf(t2), __ldg(anchors + a * 2 + 0)), 0.0f), 2.0f);
        float bh = fminf(fmaxf(__fmul_rn(expf(t3), __ldg(anchors + a * 2 + 1)), 0.0f), 2.0f);
        float x1 = __fsub_rn(bxc, __fmul_rn(0.5f, bw));
        float y1 = __fsub_rn(byc, __fmul_rn(0.5f, bh));
        float x2 = __fadd_rn(x1, bw);
        float y2 = __fadd_rn(y1, bh);
        x1 = fminf(fmaxf(x1, 0.0f), 1.0f);
        y1 = fminf(fmaxf(y1, 0.0f), 1.0f);
        x2 = fminf(fmaxf(x2, 0.0f), 1.0f);
        y2 = fminf(fmaxf(y2, 0.0f), 1.0f);

        bx[tid] = make_float4(x1, y1, x2, y2);
        float* ob = out + (size_t)t * 4;
        ob[0] = x1; ob[1] = y1; ob[2] = x2; ob[3] = y2;
        out[(size_t)BATCH * MAXDET * 4 + t] = (m >= 0.0f) ? m : 0.0f;
        out[(size_t)BATCH * MAXDET * 5 + t] = (float)g_label[(size_t)b * NCAND + idx];
    }
    __syncthreads();

    // ---- Phase B: suppression bit matrix (iou > 0.7, j > i) in parallel ----
    for (int task = tid; task < MAXDET * NWORDS; task += blockDim.x) {
        int i = task / NWORDS, w = task % NWORDS;
        float4 bi = bx[i];
        float ai = __fmul_rn(__fsub_rn(bi.z, bi.x), __fsub_rn(bi.w, bi.y));
        unsigned bits = 0;
        int j0 = w * 32;
        #pragma unroll 8
        for (int jj = 0; jj < 32; ++jj) {
            int j = j0 + jj;
            if (j > i && j < MAXDET) {
                float4 bj = bx[j];
                float lx = fmaxf(bi.x, bj.x), ly = fmaxf(bi.y, bj.y);
                float rx = fminf(bi.z, bj.z), ry = fminf(bi.w, bj.w);
                float iw = fmaxf(__fsub_rn(rx, lx), 0.0f);
                float ih = fmaxf(__fsub_rn(ry, ly), 0.0f);
                float inter = __fmul_rn(iw, ih);
                float aj = __fmul_rn(__fsub_rn(bj.z, bj.x), __fsub_rn(bj.w, bj.y));
                float den = __fadd_rn(__fsub_rn(__fadd_rn(ai, aj), inter), 1e-9f);
                float iou = __fdiv_rn(inter, den);
                if (iou > 0.7f) bits |= (1u << jj);
            }
        }
        sup[task] = bits;
    }
    __syncthreads();

    // ---- Phase C: sequential greedy scan on one warp (bit ops only) ----
    if (tid < 32) {
        int l = tid;
        unsigned kw = 0;
        if (l < NWORDS) {
            for (int jj = 0; jj < 32; ++jj) {
                int j = l * 32 + jj;
                if (j < MAXDET && g_selmask[b * MAXDET + j] >= 0.0f) kw |= (1u << jj);
            }
        }
        for (int i = 0; i < MAXDET; ++i) {
            unsigned wrd = __shfl_sync(0xFFFFFFFFu, kw, i >> 5);
            if ((wrd >> (i & 31)) & 1u) {            // warp-uniform branch
                if (l < NWORDS) kw &= ~sup[i * NWORDS + l];
            }
        }
        if (l < NWORDS) keepw_s[l] = kw;
    }
    __syncthreads();
    for (int j = tid; j < MAXDET; j += blockDim.x)
        out[(size_t)BATCH * MAXDET * 6 + b * MAXDET + j] =
            ((keepw_s[j >> 5] >> (j & 31)) & 1u) ? 1.0f : 0.0f;
}

// ================= launch =================
extern "C" void kernel_launch(void* const* d_in, const int* in_sizes, int n_in,
                              void* d_out, int out_size) {
    (void)out_size;
    const float* x       = (const float*)d_in[0];
    const float* anchors = (const float*)d_in[1];
    if (n_in >= 2) {
        if (in_sizes[1] == X_ELEMS || in_sizes[0] < in_sizes[1]) {
            x = (const float*)d_in[1]; anchors = (const float*)d_in[0];
        }
    }
    float* out = (float*)d_out;

    k_zero<<<1, 32>>>();
    dim3 g1((NQ + 127) / 128, AA, BATCH);
    k_decode<<<g1, 128>>>(x);
    k_select<<<BATCH, 1024>>>();
    k_boxnms<<<BATCH, 1024>>>(x, anchors, out);
}